// round 2
// baseline (speedup 1.0000x reference)
#include <cuda_runtime.h>
#include <cuda_bf16.h>

// Problem constants
#define BB   64
#define DPT  128
#define HW   121     // 11*11
#define OCH  16

typedef unsigned long long u64;

union F2U { u64 u; float2 f; };

__device__ __forceinline__ u64 fma2(u64 a, u64 b, u64 c) {
    u64 d;
    asm("fma.rn.f32x2 %0, %1, %2, %3;" : "=l"(d) : "l"(a), "l"(b), "l"(c));
    return d;
}

// Scratch (device globals: allocation-free)
__device__ float g_sa1[BB*OCH*DPT*HW];
__device__ float g_sa2[BB*OCH*DPT*HW];
__device__ float g_sa3[BB*OCH*DPT*HW];
__device__ float g_feat[5*BB*OCH*HW];   // 5 feats of (B,16,11,11)

#define FEAT_SZ (OCH*HW)         // 1936

// ---------------------------------------------------------------------------
// 3D conv with packed f32x2 FMAs.
// out[b,o,d,h,w] = relu(bias[o] + sum_{i,kd,kh,kw} in[b,i,d+kd-3,h+kh-1,w+kw-1]*W[o,i,kd,kh,kw])
// Block: (d-block of 8, b). 256 threads: og=tid>>7 handles 8 out-channels (4 f32x2
// pairs), pos=tid&127 spatial. Input staged in smem DUPLICATED as (v,v) float2 so a
// single LDS.64 produces the packed a-operand; weights o-contiguous so LDS.128
// produces two packed b-operand pairs. Channels processed in chunks of CHK to keep
// smem <= 102KB (2 blocks/SM).
// ---------------------------------------------------------------------------
template<int ICH, int CHK>
__global__ void __launch_bounds__(256, 2) conv3d2_kernel(
    const float* __restrict__ in, const float* __restrict__ wt,
    const float* __restrict__ bias, float* __restrict__ out)
{
    const int d0 = blockIdx.x * 8;
    const int b  = blockIdx.y;
    extern __shared__ float sm[];
    float*  w_s = sm;                          // ICH*63*16 floats
    float2* in2 = (float2*)(sm + ICH*63*16);   // CHK*14*169 + 16 float2 (dup pairs)
    const int tid = threadIdx.x;

    // stage + transpose weights: src [o][i*63+r] -> dst [(i*63+r)*16 + o]
    for (int t = tid; t < OCH*ICH*63; t += 256) {
        int o = t / (ICH*63);
        int r = t - o*(ICH*63);
        w_s[r*16 + o] = wt[t];
    }

    const int og  = tid >> 7;
    const int pos = tid & 127;
    const int cpos = pos < HW ? pos : HW-1;       // clamp dead lanes (no smem OOB)
    const int h = cpos / 11, w = cpos - h*11;
    const int ppc = (h+1)*13 + (w+1);

    u64 acc[8][4];
    #pragma unroll
    for (int r = 0; r < 8; r++)
        #pragma unroll
        for (int p = 0; p < 4; p++) acc[r][p] = 0ULL;

    for (int c0 = 0; c0 < ICH; c0 += CHK) {
        __syncthreads();
        // stage input chunk: spatial zero-pad to 13x13, depth halo d0-3..d0+10, duplicated
        for (int t = tid; t < CHK*14*169; t += 256) {
            int ii  = t / (14*169);
            int rem = t - ii*(14*169);
            int dd  = rem / 169;
            int pp  = rem - dd*169;
            int h13 = pp / 13, w13 = pp - h13*13;
            int gd  = d0 - 3 + dd;
            float v = 0.f;
            if (h13 >= 1 && h13 <= 11 && w13 >= 1 && w13 <= 11 && gd >= 0 && gd < DPT)
                v = in[((b*ICH + c0 + ii)*DPT + gd)*HW + (h13-1)*11 + (w13-1)];
            in2[t] = make_float2(v, v);
        }
        __syncthreads();

        for (int ii = 0; ii < CHK; ++ii) {
            #pragma unroll 1
            for (int kd = 0; kd < 7; ++kd) {
                const u64*   ib = (const u64*)in2 + (ii*14 + kd)*169 + ppc;
                const float* wb = w_s + ((c0 + ii)*63 + kd*9)*16 + og*8;
                #pragma unroll
                for (int khw = 0; khw < 9; ++khw) {
                    const int kh = khw / 3, kw = khw - kh*3;
                    const int off = (kh - 1)*13 + (kw - 1);
                    ulonglong2 wp0 = *reinterpret_cast<const ulonglong2*>(wb + khw*16);
                    ulonglong2 wp1 = *reinterpret_cast<const ulonglong2*>(wb + khw*16 + 4);
                    #pragma unroll
                    for (int r = 0; r < 8; ++r) {
                        u64 v = ib[r*169 + off];
                        acc[r][0] = fma2(v, wp0.x, acc[r][0]);
                        acc[r][1] = fma2(v, wp0.y, acc[r][1]);
                        acc[r][2] = fma2(v, wp1.x, acc[r][2]);
                        acc[r][3] = fma2(v, wp1.y, acc[r][3]);
                    }
                }
            }
        }
    }

    if (pos < HW) {
        #pragma unroll
        for (int p = 0; p < 4; ++p) {
            const int o = og*8 + p*2;
            const float b0 = bias[o], b1 = bias[o+1];
            #pragma unroll
            for (int r = 0; r < 8; ++r) {
                F2U a; a.u = acc[r][p];
                float v0 = a.f.x + b0;
                float v1 = a.f.y + b1;
                out[((b*OCH + o  )*DPT + (d0 + r))*HW + pos] = v0 > 0.f ? v0 : 0.f;
                out[((b*OCH + o+1)*DPT + (d0 + r))*HW + pos] = v1 > 0.f ? v1 : 0.f;
            }
        }
    }
}

// ---------------------------------------------------------------------------
// cpr: feat[b,o,p] = relu( sum_d sa[b,o,d,p] * softmax(cw[o,:])[d] )
// grid (16, 64), 128 threads
// ---------------------------------------------------------------------------
__global__ void cpr_kernel(const float* __restrict__ sa, const float* __restrict__ cw,
                           float* __restrict__ feat)
{
    const int o = blockIdx.x, b = blockIdx.y, tid = threadIdx.x;
    __shared__ float a_s[128];
    __shared__ float red[128];
    float wv = cw[o*128 + tid];
    red[tid] = wv; __syncthreads();
    for (int s = 64; s > 0; s >>= 1) { if (tid < s) red[tid] = fmaxf(red[tid], red[tid+s]); __syncthreads(); }
    float mx = red[0]; __syncthreads();
    float e = expf(wv - mx);
    red[tid] = e; __syncthreads();
    for (int s = 64; s > 0; s >>= 1) { if (tid < s) red[tid] += red[tid+s]; __syncthreads(); }
    a_s[tid] = e / red[0];
    __syncthreads();
    if (tid < HW) {
        const float* base = sa + ((size_t)(b*16 + o)*DPT)*HW + tid;
        float acc = 0.f;
        #pragma unroll 4
        for (int d = 0; d < 128; ++d) acc += base[d*HW] * a_s[d];
        feat[(b*16 + o)*HW + tid] = acc > 0.f ? acc : 0.f;
    }
}

// ---------------------------------------------------------------------------
// conv4/conv5 2D: relu(conv2d(3x3,pad1)) twice. One block per batch.
// ---------------------------------------------------------------------------
__global__ void conv45_kernel(const float* __restrict__ feat2,
                              const float* __restrict__ w45, const float* __restrict__ b45,
                              float* __restrict__ feat3, float* __restrict__ feat4)
{
    const int b = blockIdx.x, tid = threadIdx.x;
    __shared__ float fa[FEAT_SZ], fb[FEAT_SZ];
    for (int t = tid; t < FEAT_SZ; t += 128) fa[t] = feat2[b*FEAT_SZ + t];
    __syncthreads();
    if (tid < HW) {
        int h = tid / 11, w = tid - h*11;
        for (int o = 0; o < 16; o++) {
            float acc = b45[o];
            for (int c = 0; c < 16; c++)
                #pragma unroll
                for (int kh = 0; kh < 3; kh++) {
                    int hh = h + kh - 1; if (hh < 0 || hh >= 11) continue;
                    #pragma unroll
                    for (int kw = 0; kw < 3; kw++) {
                        int ww2 = w + kw - 1; if (ww2 < 0 || ww2 >= 11) continue;
                        acc += fa[c*HW + hh*11 + ww2] * w45[(o*16 + c)*9 + kh*3 + kw];
                    }
                }
            float v = acc > 0.f ? acc : 0.f;
            fb[o*HW + tid] = v;
            feat3[b*FEAT_SZ + o*HW + tid] = v;
        }
    }
    __syncthreads();
    if (tid < HW) {
        int h = tid / 11, w = tid - h*11;
        for (int o = 0; o < 16; o++) {
            float acc = b45[16 + o];
            for (int c = 0; c < 16; c++)
                #pragma unroll
                for (int kh = 0; kh < 3; kh++) {
                    int hh = h + kh - 1; if (hh < 0 || hh >= 11) continue;
                    #pragma unroll
                    for (int kw = 0; kw < 3; kw++) {
                        int ww2 = w + kw - 1; if (ww2 < 0 || ww2 >= 11) continue;
                        acc += fb[c*HW + hh*11 + ww2] * w45[2304 + (o*16 + c)*9 + kh*3 + kw];
                    }
                }
            float v = acc > 0.f ? acc : 0.f;
            feat4[b*FEAT_SZ + o*HW + tid] = v;
        }
    }
}

// ---------------------------------------------------------------------------
// Side head: per (side i, batch b). Sideout, seg conv, top-5 similar sum,
// receptive-field-reduced sp branch (only 7x7 ratio patch matters), fuse.
// ---------------------------------------------------------------------------
__global__ void side_kernel(const float* __restrict__ x, const float* __restrict__ feat,
    const float* __restrict__ sw,  const float* __restrict__ sb,
    const float* __restrict__ sow, const float* __restrict__ sob,
    const float* __restrict__ wa,  const float* __restrict__ ba,
    const float* __restrict__ wb,  const float* __restrict__ bbv,
    const float* __restrict__ ssw, const float* __restrict__ ssb,
    const float* __restrict__ fuse, float* __restrict__ out)
{
    const int i = blockIdx.x, b = blockIdx.y, tid = threadIdx.x;
    __shared__ float f_s[FEAT_SZ], act_s[HW], diff_s[HW], s_arr[128], xc[128], y1_s[144], y2_s[16];
    __shared__ int idx_s[5];

    for (int t = tid; t < FEAT_SZ; t += 128)
        f_s[t] = feat[i*(BB*FEAT_SZ) + b*FEAT_SZ + t];
    __syncthreads();

    // seg conv (no relu)
    if (tid < HW) {
        int h = tid / 11, w = tid - h*11;
        float acc = sb[i];
        for (int c = 0; c < 16; c++)
            #pragma unroll
            for (int kh = 0; kh < 3; kh++) {
                int hh = h + kh - 1; if (hh < 0 || hh >= 11) continue;
                #pragma unroll
                for (int kw = 0; kw < 3; kw++) {
                    int ww2 = w + kw - 1; if (ww2 < 0 || ww2 >= 11) continue;
                    acc += f_s[c*HW + hh*11 + ww2] * sw[(i*16 + c)*9 + kh*3 + kw];
                }
            }
        act_s[tid] = acc;
    }
    __syncthreads();
    if (tid < HW) diff_s[tid] = fabsf(act_s[tid] - act_s[60]);
    __syncthreads();
    // top-5 smallest diff, stable (lowest index on ties) — matches jax top_k(-diff)
    if (tid == 0) {
        for (int j = 0; j < 5; j++) {
            float best = 3.4e38f; int bi = 0;
            for (int p = 0; p < HW; p++) { float d = diff_s[p]; if (d < best) { best = d; bi = p; } }
            idx_s[j] = bi; diff_s[bi] = 3.4e38f;
        }
    }
    __syncthreads();
    // similar-sum s[c] and center xc[c]
    {
        float s = 0.f;
        const float* xb = x + (size_t)(b*128 + tid)*HW;
        #pragma unroll
        for (int j = 0; j < 5; j++) s += xb[idx_s[j]];
        s_arr[tid] = s;
        xc[tid] = xb[60];
    }
    __syncthreads();
    // y1 at the 9 positions {62,64,66}^2 feeding the dil-2 conv center
    for (int t = tid; t < 144; t += 128) {
        int o = t / 9, j = t - o*9;
        int pj = 62 + 2*(j/3), qj = 62 + 2*(j%3);
        float acc = ba[i*16 + o];
        #pragma unroll
        for (int ch = 0; ch < 2; ch++) {
            const float* num = ch ? xc : s_arr;
            #pragma unroll
            for (int eh = 0; eh < 3; eh++)
                #pragma unroll
                for (int ew = 0; ew < 3; ew++) {
                    int r = pj + eh - 1, c = qj + ew - 1;
                    float den = num[c];
                    den = fabsf(den) < 0.01f ? 0.01f : den;
                    float img = num[r] / den;
                    acc += img * wa[(((i*16 + o)*2 + ch)*3 + eh)*3 + ew];
                }
        }
        y1_s[o*9 + j] = acc > 0.f ? acc : 0.f;
    }
    __syncthreads();
    // y2 center (dil-2 conv), relu
    if (tid < 16) {
        float acc = bbv[i*16 + tid];
        for (int c = 0; c < 16; c++)
            #pragma unroll
            for (int j = 0; j < 9; j++)
                acc += y1_s[c*9 + j] * wb[((i*16 + tid)*16 + c)*9 + j];
        y2_s[tid] = acc > 0.f ? acc : 0.f;
    }
    __syncthreads();
    // sideouts + fuse
    if (tid < 16) {
        float sa_v = sob[i*16 + tid];
        for (int k = 0; k < 16; k++) sa_v += f_s[k*HW + 60] * sow[(i*16 + tid)*16 + k];
        float sp_v = ssb[i*16 + tid];
        for (int c = 0; c < 16; c++) sp_v += y2_s[c] * ssw[(i*16 + tid)*16 + c];
        atomicAdd(&out[b*16 + tid], fuse[i]*sa_v + fuse[5 + i]*sp_v);
    }
}

__global__ void zero_kernel(float* out, int n)
{
    int t = blockIdx.x*blockDim.x + threadIdx.x;
    if (t < n) out[t] = 0.f;
}

// ---------------------------------------------------------------------------
extern "C" void kernel_launch(void* const* d_in, const int* in_sizes, int n_in,
                              void* d_out, int out_size)
{
    const float* x      = (const float*)d_in[0];
    const float* w3d1   = (const float*)d_in[1];
    const float* b3d1   = (const float*)d_in[2];
    const float* w3d23  = (const float*)d_in[3];
    const float* b3d23  = (const float*)d_in[4];
    const float* cpr_w  = (const float*)d_in[5];
    const float* w2d45  = (const float*)d_in[6];
    const float* b2d45  = (const float*)d_in[7];
    const float* seg_w  = (const float*)d_in[8];
    const float* seg_b  = (const float*)d_in[9];
    const float* so_w   = (const float*)d_in[10];
    const float* so_b   = (const float*)d_in[11];
    const float* sp_wa  = (const float*)d_in[12];
    const float* sp_ba  = (const float*)d_in[13];
    const float* sp_wb  = (const float*)d_in[14];
    const float* sp_bb  = (const float*)d_in[15];
    const float* sp_sw  = (const float*)d_in[16];
    const float* sp_sb  = (const float*)d_in[17];
    const float* fuse   = (const float*)d_in[18];
    float* out = (float*)d_out;

    float *sa1, *sa2, *sa3, *feat;
    cudaGetSymbolAddress((void**)&sa1,  g_sa1);
    cudaGetSymbolAddress((void**)&sa2,  g_sa2);
    cudaGetSymbolAddress((void**)&sa3,  g_sa3);
    cudaGetSymbolAddress((void**)&feat, g_feat);

    // smem: weights + duplicated (f32x2) input chunk (+16 float2 pad)
    const int SMEM16 = 16*63*16*4 + (2*14*169 + 16)*8;  // 102496 B -> 2 blocks/SM
    const int SMEM1  = 1*63*16*4  + (1*14*169 + 16)*8;  // 23088 B
    cudaFuncSetAttribute((const void*)conv3d2_kernel<16,2>, cudaFuncAttributeMaxDynamicSharedMemorySize, SMEM16);
    cudaFuncSetAttribute((const void*)conv3d2_kernel<1,1>,  cudaFuncAttributeMaxDynamicSharedMemorySize, SMEM1);

    zero_kernel<<<(out_size + 255)/256, 256>>>(out, out_size);

    conv3d2_kernel<1,1><<<dim3(16, BB), 256, SMEM1>>>(x, w3d1, b3d1, sa1);
    cpr_kernel<<<dim3(16, BB), 128>>>(sa1, cpr_w + 0*2048, feat + 0*(BB*FEAT_SZ));

    conv3d2_kernel<16,2><<<dim3(16, BB), 256, SMEM16>>>(sa1, w3d23, b3d23, sa2);
    cpr_kernel<<<dim3(16, BB), 128>>>(sa2, cpr_w + 1*2048, feat + 1*(BB*FEAT_SZ));

    conv3d2_kernel<16,2><<<dim3(16, BB), 256, SMEM16>>>(sa2, w3d23 + 16128, b3d23 + 16, sa3);
    cpr_kernel<<<dim3(16, BB), 128>>>(sa3, cpr_w + 2*2048, feat + 2*(BB*FEAT_SZ));

    conv45_kernel<<<BB, 128>>>(feat + 2*(BB*FEAT_SZ), w2d45, b2d45,
                               feat + 3*(BB*FEAT_SZ), feat + 4*(BB*FEAT_SZ));

    side_kernel<<<dim3(5, BB), 128>>>(x, feat, seg_w, seg_b, so_w, so_b,
                                      sp_wa, sp_ba, sp_wb, sp_bb, sp_sw, sp_sb,
                                      fuse, out);
}

// round 3
// speedup vs baseline: 1.2365x; 1.2365x over previous
#include <cuda_runtime.h>
#include <cuda_bf16.h>

// Problem constants
#define BB   64
#define DPT  128
#define HW   121     // 11*11
#define OCH  16

typedef unsigned long long u64;

union F2U { u64 u; float2 f; };

__device__ __forceinline__ u64 fma2(u64 a, u64 b, u64 c) {
    u64 d;
    asm("fma.rn.f32x2 %0, %1, %2, %3;" : "=l"(d) : "l"(a), "l"(b), "l"(c));
    return d;
}

// Scratch (device globals: allocation-free)
__device__ float g_sa1[BB*OCH*DPT*HW];
__device__ float g_sa2[BB*OCH*DPT*HW];
__device__ float g_sa3[BB*OCH*DPT*HW];
__device__ float g_feat[5*BB*OCH*HW];   // 5 feats of (B,16,11,11)

#define FEAT_SZ (OCH*HW)         // 1936

// ---------------------------------------------------------------------------
// 3D conv, packed f32x2 FMAs over DEPTH PAIRS.
// out[b,o,d,h,w] = relu(bias[o] + sum_{i,kd,kh,kw} in[b,i,d+kd-3,h+kh-1,w+kw-1]*W[o,i,kd,kh,kw])
//
// Block: (d-block of 8, b). 256 threads: og=tid>>7 -> 8 out-channels,
// pos=tid&127 spatial. Each thread computes 4 depth-PAIRS x 8 channels.
// smem input: rows dd=0..12 of consecutive-depth pairs (in[d0-3+dd], in[d0-3+dd+1])
//   -> one LDS.64 feeds two output depths (both packed lanes do real work).
// smem weights: duplicated (w,w) float2, o-contiguous; addresses warp-uniform
//   -> broadcast LDS (no crossbar pressure).
// Channels processed in chunks of CHK (input AND weights staged per chunk).
// ---------------------------------------------------------------------------
template<int ICH, int CHK>
__global__ void __launch_bounds__(256, 2) conv3d3_kernel(
    const float* __restrict__ in, const float* __restrict__ wt,
    const float* __restrict__ bias, float* __restrict__ out)
{
    const int d0 = blockIdx.x * 8;
    const int b  = blockIdx.y;
    extern __shared__ float2 sm2[];
    float2* w2_s = sm2;                     // CHK*63*16 float2 (dup weights)
    float2* in2  = sm2 + CHK*63*16;         // CHK*13*169 float2 (depth pairs)
    const int tid = threadIdx.x;

    const int og  = tid >> 7;
    const int pos = tid & 127;
    const int cpos = pos < HW ? pos : HW-1;       // clamp dead lanes (no smem OOB)
    const int h = cpos / 11, w = cpos - h*11;
    const int ppc = (h+1)*13 + (w+1);

    u64 acc[4][8];   // [depth-pair][out-channel]
    #pragma unroll
    for (int r = 0; r < 4; r++)
        #pragma unroll
        for (int o = 0; o < 8; o++) acc[r][o] = 0ULL;

    for (int c0 = 0; c0 < ICH; c0 += CHK) {
        __syncthreads();
        // stage weights (duplicated): src wt[o][(c0+ii)*63 + r] -> w2_s[(ii*63+r)*16+o]=(v,v)
        for (int t = tid; t < OCH*CHK*63; t += 256) {
            int o = t / (CHK*63);
            int r = t - o*(CHK*63);
            float v = wt[o*(ICH*63) + c0*63 + r];
            w2_s[r*16 + o] = make_float2(v, v);
        }
        // stage input depth-pairs: rows dd=0..12, value (in[gd], in[gd+1]), gd=d0-3+dd
        for (int t = tid; t < CHK*13*169; t += 256) {
            int ii  = t / (13*169);
            int rem = t - ii*(13*169);
            int dd  = rem / 169;
            int pp  = rem - dd*169;
            int h13 = pp / 13, w13 = pp - h13*13;
            int gd  = d0 - 3 + dd;
            float v0 = 0.f, v1 = 0.f;
            if (h13 >= 1 && h13 <= 11 && w13 >= 1 && w13 <= 11) {
                const float* src = in + ((size_t)(b*ICH + c0 + ii)*DPT)*HW + (h13-1)*11 + (w13-1);
                if (gd   >= 0 && gd   < DPT) v0 = src[(size_t)gd*HW];
                if (gd+1 >= 0 && gd+1 < DPT) v1 = src[(size_t)(gd+1)*HW];
            }
            in2[t] = make_float2(v0, v1);
        }
        __syncthreads();

        for (int ii = 0; ii < CHK; ++ii) {
            #pragma unroll 1
            for (int kd = 0; kd < 7; ++kd) {
                const u64* ib = (const u64*)in2 + (ii*13 + kd)*169 + ppc;
                const u64* wb = (const u64*)w2_s + (ii*63 + kd*9)*16 + og*8;
                #pragma unroll
                for (int khw = 0; khw < 9; ++khw) {
                    const int kh = khw / 3, kw = khw - kh*3;
                    const int off = (kh - 1)*13 + (kw - 1);
                    // broadcast weight loads (warp-uniform address)
                    ulonglong2 w01 = *reinterpret_cast<const ulonglong2*>(wb + khw*16);
                    ulonglong2 w23 = *reinterpret_cast<const ulonglong2*>(wb + khw*16 + 2);
                    ulonglong2 w45 = *reinterpret_cast<const ulonglong2*>(wb + khw*16 + 4);
                    ulonglong2 w67 = *reinterpret_cast<const ulonglong2*>(wb + khw*16 + 6);
                    u64 wd[8] = {w01.x, w01.y, w23.x, w23.y, w45.x, w45.y, w67.x, w67.y};
                    #pragma unroll
                    for (int r = 0; r < 4; ++r) {
                        u64 a = ib[(2*r)*169 + off];   // depths (d0+2r+kd-3, +1)
                        #pragma unroll
                        for (int o = 0; o < 8; ++o)
                            acc[r][o] = fma2(a, wd[o], acc[r][o]);
                    }
                }
            }
        }
    }

    if (pos < HW) {
        #pragma unroll
        for (int o = 0; o < 8; ++o) {
            const int oc = og*8 + o;
            const float bv = bias[oc];
            float* ob = out + ((size_t)(b*OCH + oc)*DPT + d0)*HW + pos;
            #pragma unroll
            for (int r = 0; r < 4; ++r) {
                F2U a; a.u = acc[r][o];
                float v0 = a.f.x + bv;
                float v1 = a.f.y + bv;
                ob[(2*r  )*HW] = v0 > 0.f ? v0 : 0.f;
                ob[(2*r+1)*HW] = v1 > 0.f ? v1 : 0.f;
            }
        }
    }
}

// ---------------------------------------------------------------------------
// cpr: feat[b,o,p] = relu( sum_d sa[b,o,d,p] * softmax(cw[o,:])[d] )
// ---------------------------------------------------------------------------
__global__ void cpr_kernel(const float* __restrict__ sa, const float* __restrict__ cw,
                           float* __restrict__ feat)
{
    const int o = blockIdx.x, b = blockIdx.y, tid = threadIdx.x;
    __shared__ float a_s[128];
    __shared__ float red[128];
    float wv = cw[o*128 + tid];
    red[tid] = wv; __syncthreads();
    for (int s = 64; s > 0; s >>= 1) { if (tid < s) red[tid] = fmaxf(red[tid], red[tid+s]); __syncthreads(); }
    float mx = red[0]; __syncthreads();
    float e = expf(wv - mx);
    red[tid] = e; __syncthreads();
    for (int s = 64; s > 0; s >>= 1) { if (tid < s) red[tid] += red[tid+s]; __syncthreads(); }
    a_s[tid] = e / red[0];
    __syncthreads();
    if (tid < HW) {
        const float* base = sa + ((size_t)(b*16 + o)*DPT)*HW + tid;
        float acc = 0.f;
        #pragma unroll 4
        for (int d = 0; d < 128; ++d) acc += base[d*HW] * a_s[d];
        feat[(b*16 + o)*HW + tid] = acc > 0.f ? acc : 0.f;
    }
}

// ---------------------------------------------------------------------------
// conv4/conv5 2D: relu(conv2d(3x3,pad1)) twice. One block per batch.
// ---------------------------------------------------------------------------
__global__ void conv45_kernel(const float* __restrict__ feat2,
                              const float* __restrict__ w45, const float* __restrict__ b45,
                              float* __restrict__ feat3, float* __restrict__ feat4)
{
    const int b = blockIdx.x, tid = threadIdx.x;
    __shared__ float fa[FEAT_SZ], fb[FEAT_SZ];
    for (int t = tid; t < FEAT_SZ; t += 128) fa[t] = feat2[b*FEAT_SZ + t];
    __syncthreads();
    if (tid < HW) {
        int h = tid / 11, w = tid - h*11;
        for (int o = 0; o < 16; o++) {
            float acc = b45[o];
            for (int c = 0; c < 16; c++)
                #pragma unroll
                for (int kh = 0; kh < 3; kh++) {
                    int hh = h + kh - 1; if (hh < 0 || hh >= 11) continue;
                    #pragma unroll
                    for (int kw = 0; kw < 3; kw++) {
                        int ww2 = w + kw - 1; if (ww2 < 0 || ww2 >= 11) continue;
                        acc += fa[c*HW + hh*11 + ww2] * w45[(o*16 + c)*9 + kh*3 + kw];
                    }
                }
            float v = acc > 0.f ? acc : 0.f;
            fb[o*HW + tid] = v;
            feat3[b*FEAT_SZ + o*HW + tid] = v;
        }
    }
    __syncthreads();
    if (tid < HW) {
        int h = tid / 11, w = tid - h*11;
        for (int o = 0; o < 16; o++) {
            float acc = b45[16 + o];
            for (int c = 0; c < 16; c++)
                #pragma unroll
                for (int kh = 0; kh < 3; kh++) {
                    int hh = h + kh - 1; if (hh < 0 || hh >= 11) continue;
                    #pragma unroll
                    for (int kw = 0; kw < 3; kw++) {
                        int ww2 = w + kw - 1; if (ww2 < 0 || ww2 >= 11) continue;
                        acc += fb[c*HW + hh*11 + ww2] * w45[2304 + (o*16 + c)*9 + kh*3 + kw];
                    }
                }
            float v = acc > 0.f ? acc : 0.f;
            feat4[b*FEAT_SZ + o*HW + tid] = v;
        }
    }
}

// ---------------------------------------------------------------------------
// Side head: per (side i, batch b). Sideout, seg conv, top-5 similar sum,
// receptive-field-reduced sp branch (only 7x7 ratio patch matters), fuse.
// ---------------------------------------------------------------------------
__global__ void side_kernel(const float* __restrict__ x, const float* __restrict__ feat,
    const float* __restrict__ sw,  const float* __restrict__ sb,
    const float* __restrict__ sow, const float* __restrict__ sob,
    const float* __restrict__ wa,  const float* __restrict__ ba,
    const float* __restrict__ wb,  const float* __restrict__ bbv,
    const float* __restrict__ ssw, const float* __restrict__ ssb,
    const float* __restrict__ fuse, float* __restrict__ out)
{
    const int i = blockIdx.x, b = blockIdx.y, tid = threadIdx.x;
    __shared__ float f_s[FEAT_SZ], act_s[HW], diff_s[HW], s_arr[128], xc[128], y1_s[144], y2_s[16];
    __shared__ int idx_s[5];

    for (int t = tid; t < FEAT_SZ; t += 128)
        f_s[t] = feat[i*(BB*FEAT_SZ) + b*FEAT_SZ + t];
    __syncthreads();

    // seg conv (no relu)
    if (tid < HW) {
        int h = tid / 11, w = tid - h*11;
        float acc = sb[i];
        for (int c = 0; c < 16; c++)
            #pragma unroll
            for (int kh = 0; kh < 3; kh++) {
                int hh = h + kh - 1; if (hh < 0 || hh >= 11) continue;
                #pragma unroll
                for (int kw = 0; kw < 3; kw++) {
                    int ww2 = w + kw - 1; if (ww2 < 0 || ww2 >= 11) continue;
                    acc += f_s[c*HW + hh*11 + ww2] * sw[(i*16 + c)*9 + kh*3 + kw];
                }
            }
        act_s[tid] = acc;
    }
    __syncthreads();
    if (tid < HW) diff_s[tid] = fabsf(act_s[tid] - act_s[60]);
    __syncthreads();
    // top-5 smallest diff, stable (lowest index on ties) — matches jax top_k(-diff)
    if (tid == 0) {
        for (int j = 0; j < 5; j++) {
            float best = 3.4e38f; int bi = 0;
            for (int p = 0; p < HW; p++) { float d = diff_s[p]; if (d < best) { best = d; bi = p; } }
            idx_s[j] = bi; diff_s[bi] = 3.4e38f;
        }
    }
    __syncthreads();
    // similar-sum s[c] and center xc[c]
    {
        float s = 0.f;
        const float* xb = x + (size_t)(b*128 + tid)*HW;
        #pragma unroll
        for (int j = 0; j < 5; j++) s += xb[idx_s[j]];
        s_arr[tid] = s;
        xc[tid] = xb[60];
    }
    __syncthreads();
    // y1 at the 9 positions {62,64,66}^2 feeding the dil-2 conv center
    for (int t = tid; t < 144; t += 128) {
        int o = t / 9, j = t - o*9;
        int pj = 62 + 2*(j/3), qj = 62 + 2*(j%3);
        float acc = ba[i*16 + o];
        #pragma unroll
        for (int ch = 0; ch < 2; ch++) {
            const float* num = ch ? xc : s_arr;
            #pragma unroll
            for (int eh = 0; eh < 3; eh++)
                #pragma unroll
                for (int ew = 0; ew < 3; ew++) {
                    int r = pj + eh - 1, c = qj + ew - 1;
                    float den = num[c];
                    den = fabsf(den) < 0.01f ? 0.01f : den;
                    float img = num[r] / den;
                    acc += img * wa[(((i*16 + o)*2 + ch)*3 + eh)*3 + ew];
                }
        }
        y1_s[o*9 + j] = acc > 0.f ? acc : 0.f;
    }
    __syncthreads();
    // y2 center (dil-2 conv), relu
    if (tid < 16) {
        float acc = bbv[i*16 + tid];
        for (int c = 0; c < 16; c++)
            #pragma unroll
            for (int j = 0; j < 9; j++)
                acc += y1_s[c*9 + j] * wb[((i*16 + tid)*16 + c)*9 + j];
        y2_s[tid] = acc > 0.f ? acc : 0.f;
    }
    __syncthreads();
    // sideouts + fuse
    if (tid < 16) {
        float sa_v = sob[i*16 + tid];
        for (int k = 0; k < 16; k++) sa_v += f_s[k*HW + 60] * sow[(i*16 + tid)*16 + k];
        float sp_v = ssb[i*16 + tid];
        for (int c = 0; c < 16; c++) sp_v += y2_s[c] * ssw[(i*16 + tid)*16 + c];
        atomicAdd(&out[b*16 + tid], fuse[i]*sa_v + fuse[5 + i]*sp_v);
    }
}

__global__ void zero_kernel(float* out, int n)
{
    int t = blockIdx.x*blockDim.x + threadIdx.x;
    if (t < n) out[t] = 0.f;
}

// ---------------------------------------------------------------------------
extern "C" void kernel_launch(void* const* d_in, const int* in_sizes, int n_in,
                              void* d_out, int out_size)
{
    const float* x      = (const float*)d_in[0];
    const float* w3d1   = (const float*)d_in[1];
    const float* b3d1   = (const float*)d_in[2];
    const float* w3d23  = (const float*)d_in[3];
    const float* b3d23  = (const float*)d_in[4];
    const float* cpr_w  = (const float*)d_in[5];
    const float* w2d45  = (const float*)d_in[6];
    const float* b2d45  = (const float*)d_in[7];
    const float* seg_w  = (const float*)d_in[8];
    const float* seg_b  = (const float*)d_in[9];
    const float* so_w   = (const float*)d_in[10];
    const float* so_b   = (const float*)d_in[11];
    const float* sp_wa  = (const float*)d_in[12];
    const float* sp_ba  = (const float*)d_in[13];
    const float* sp_wb  = (const float*)d_in[14];
    const float* sp_bb  = (const float*)d_in[15];
    const float* sp_sw  = (const float*)d_in[16];
    const float* sp_sb  = (const float*)d_in[17];
    const float* fuse   = (const float*)d_in[18];
    float* out = (float*)d_out;

    float *sa1, *sa2, *sa3, *feat;
    cudaGetSymbolAddress((void**)&sa1,  g_sa1);
    cudaGetSymbolAddress((void**)&sa2,  g_sa2);
    cudaGetSymbolAddress((void**)&sa3,  g_sa3);
    cudaGetSymbolAddress((void**)&feat, g_feat);

    // smem: dup weights chunk + depth-pair input chunk (float2 each)
    const int SMEM16 = (4*63*16 + 4*13*169) * 8;   // CHK=4 -> 102,560 B (2 blocks/SM)
    const int SMEM1  = (1*63*16 + 1*13*169) * 8;   // 25,640 B
    cudaFuncSetAttribute((const void*)conv3d3_kernel<16,4>, cudaFuncAttributeMaxDynamicSharedMemorySize, SMEM16);
    cudaFuncSetAttribute((const void*)conv3d3_kernel<1,1>,  cudaFuncAttributeMaxDynamicSharedMemorySize, SMEM1);

    zero_kernel<<<(out_size + 255)/256, 256>>>(out, out_size);

    conv3d3_kernel<1,1><<<dim3(16, BB), 256, SMEM1>>>(x, w3d1, b3d1, sa1);
    cpr_kernel<<<dim3(16, BB), 128>>>(sa1, cpr_w + 0*2048, feat + 0*(BB*FEAT_SZ));

    conv3d3_kernel<16,4><<<dim3(16, BB), 256, SMEM16>>>(sa1, w3d23, b3d23, sa2);
    cpr_kernel<<<dim3(16, BB), 128>>>(sa2, cpr_w + 1*2048, feat + 1*(BB*FEAT_SZ));

    conv3d3_kernel<16,4><<<dim3(16, BB), 256, SMEM16>>>(sa2, w3d23 + 16128, b3d23 + 16, sa3);
    cpr_kernel<<<dim3(16, BB), 128>>>(sa3, cpr_w + 2*2048, feat + 2*(BB*FEAT_SZ));

    conv45_kernel<<<BB, 128>>>(feat + 2*(BB*FEAT_SZ), w2d45, b2d45,
                               feat + 3*(BB*FEAT_SZ), feat + 4*(BB*FEAT_SZ));

    side_kernel<<<dim3(5, BB), 128>>>(x, feat, seg_w, seg_b, so_w, so_b,
                                      sp_wa, sp_ba, sp_wb, sp_bb, sp_sw, sp_sb,
                                      fuse, out);
}

// round 4
// speedup vs baseline: 1.4361x; 1.1615x over previous
#include <cuda_runtime.h>
#include <cuda_bf16.h>

// Problem constants
#define BB   64
#define DPT  128
#define HW   121     // 11*11
#define OCH  16

typedef unsigned long long u64;

union F2U { u64 u; float2 f; };

__device__ __forceinline__ u64 fma2(u64 a, u64 b, u64 c) {
    u64 d;
    asm("fma.rn.f32x2 %0, %1, %2, %3;" : "=l"(d) : "l"(a), "l"(b), "l"(c));
    return d;
}
__device__ __forceinline__ u64 dup2(float w) {
    u64 d;
    asm("mov.b64 %0, {%1, %1};" : "=l"(d) : "f"(w));
    return d;
}

// Scratch (device globals: allocation-free)
__device__ float g_sa1[BB*OCH*DPT*HW];
__device__ float g_sa2[BB*OCH*DPT*HW];
__device__ float g_sa3[BB*OCH*DPT*HW];
__device__ float g_feat[5*BB*OCH*HW];   // 5 feats of (B,16,11,11)

#define FEAT_SZ (OCH*HW)         // 1936

// ---------------------------------------------------------------------------
// 3D conv, packed f32x2 FMAs over DEPTH PAIRS.
// out[b,o,d,h,w] = relu(bias[o] + sum_{i,kd,kh,kw} in[b,i,d+kd-3,h+kh-1,w+kw-1]*W[o,i,kd,kh,kw])
//
// Block: (d-block of 8, b). 256 threads: og=tid>>7 -> 8 out-channels,
// pos=tid&127 spatial. Each thread computes 4 depth-PAIRS x 8 channels.
// smem input: rows dd=0..12 of consecutive-depth pairs (in[d0-3+dd], in[d0-3+dd+1])
//   -> one LDS.64 feeds two output depths (both packed lanes do real work).
// smem weights: NON-duplicated floats, o-contiguous (uniform LDS.128, half the
//   return bytes); packed (w,w) operands built with mov.b64 on the ALU pipe.
// Channels processed in chunks of CHK (input AND weights staged per chunk).
// ---------------------------------------------------------------------------
template<int ICH, int CHK>
__global__ void __launch_bounds__(256, 2) conv3d4_kernel(
    const float* __restrict__ in, const float* __restrict__ wt,
    const float* __restrict__ bias, float* __restrict__ out)
{
    const int d0 = blockIdx.x * 8;
    const int b  = blockIdx.y;
    extern __shared__ float sm[];
    float*  w_s = sm;                               // CHK*63*16 floats
    float2* in2 = (float2*)(sm + CHK*63*16);        // CHK*13*169 float2 (depth pairs)
    const int tid = threadIdx.x;

    const int og  = tid >> 7;
    const int pos = tid & 127;
    const int cpos = pos < HW ? pos : HW-1;       // clamp dead lanes (no smem OOB)
    const int h = cpos / 11, w = cpos - h*11;
    const int ppc = (h+1)*13 + (w+1);

    u64 acc[4][8];   // [depth-pair][out-channel]
    #pragma unroll
    for (int r = 0; r < 4; r++)
        #pragma unroll
        for (int o = 0; o < 8; o++) acc[r][o] = 0ULL;

    for (int c0 = 0; c0 < ICH; c0 += CHK) {
        __syncthreads();
        // stage weights: src wt[o][(c0+ii)*63 + r] -> w_s[(ii*63+r)*16 + o]
        for (int t = tid; t < OCH*CHK*63; t += 256) {
            int o = t / (CHK*63);
            int r = t - o*(CHK*63);
            w_s[r*16 + o] = wt[o*(ICH*63) + c0*63 + r];
        }
        // stage input depth-pairs: rows dd=0..12, value (in[gd], in[gd+1]), gd=d0-3+dd
        for (int t = tid; t < CHK*13*169; t += 256) {
            int ii  = t / (13*169);
            int rem = t - ii*(13*169);
            int dd  = rem / 169;
            int pp  = rem - dd*169;
            int h13 = pp / 13, w13 = pp - h13*13;
            int gd  = d0 - 3 + dd;
            float v0 = 0.f, v1 = 0.f;
            if (h13 >= 1 && h13 <= 11 && w13 >= 1 && w13 <= 11) {
                const float* src = in + ((size_t)(b*ICH + c0 + ii)*DPT)*HW + (h13-1)*11 + (w13-1);
                if (gd   >= 0 && gd   < DPT) v0 = src[(size_t)gd*HW];
                if (gd+1 >= 0 && gd+1 < DPT) v1 = src[(size_t)(gd+1)*HW];
            }
            in2[t] = make_float2(v0, v1);
        }
        __syncthreads();

        for (int ii = 0; ii < CHK; ++ii) {
            #pragma unroll 1
            for (int kd = 0; kd < 7; ++kd) {
                const u64*   ib = (const u64*)in2 + (ii*13 + kd)*169 + ppc;
                const float* wb = w_s + ((ii*63 + kd*9))*16 + og*8;
                #pragma unroll
                for (int khw = 0; khw < 9; ++khw) {
                    const int kh = khw / 3, kw = khw - kh*3;
                    const int off = (kh - 1)*13 + (kw - 1);
                    // uniform (per-warp) weight loads, non-duplicated
                    float4 wa = *reinterpret_cast<const float4*>(wb + khw*16);
                    float4 wc = *reinterpret_cast<const float4*>(wb + khw*16 + 4);
                    u64 wd[8];
                    wd[0] = dup2(wa.x); wd[1] = dup2(wa.y);
                    wd[2] = dup2(wa.z); wd[3] = dup2(wa.w);
                    wd[4] = dup2(wc.x); wd[5] = dup2(wc.y);
                    wd[6] = dup2(wc.z); wd[7] = dup2(wc.w);
                    #pragma unroll
                    for (int r = 0; r < 4; ++r) {
                        u64 a = ib[(2*r)*169 + off];   // depths (d0+2r+kd-3, +1)
                        #pragma unroll
                        for (int o = 0; o < 8; ++o)
                            acc[r][o] = fma2(a, wd[o], acc[r][o]);
                    }
                }
            }
        }
    }

    if (pos < HW) {
        #pragma unroll
        for (int o = 0; o < 8; ++o) {
            const int oc = og*8 + o;
            const float bv = bias[oc];
            float* ob = out + ((size_t)(b*OCH + oc)*DPT + d0)*HW + pos;
            #pragma unroll
            for (int r = 0; r < 4; ++r) {
                F2U a; a.u = acc[r][o];
                float v0 = a.f.x + bv;
                float v1 = a.f.y + bv;
                ob[(2*r  )*HW] = v0 > 0.f ? v0 : 0.f;
                ob[(2*r+1)*HW] = v1 > 0.f ? v1 : 0.f;
            }
        }
    }
}

// ---------------------------------------------------------------------------
// cpr: feat[b,o,p] = relu( sum_d sa[b,o,d,p] * softmax(cw[o,:])[d] )
// ---------------------------------------------------------------------------
__global__ void cpr_kernel(const float* __restrict__ sa, const float* __restrict__ cw,
                           float* __restrict__ feat)
{
    const int o = blockIdx.x, b = blockIdx.y, tid = threadIdx.x;
    __shared__ float a_s[128];
    __shared__ float red[128];
    float wv = cw[o*128 + tid];
    red[tid] = wv; __syncthreads();
    for (int s = 64; s > 0; s >>= 1) { if (tid < s) red[tid] = fmaxf(red[tid], red[tid+s]); __syncthreads(); }
    float mx = red[0]; __syncthreads();
    float e = expf(wv - mx);
    red[tid] = e; __syncthreads();
    for (int s = 64; s > 0; s >>= 1) { if (tid < s) red[tid] += red[tid+s]; __syncthreads(); }
    a_s[tid] = e / red[0];
    __syncthreads();
    if (tid < HW) {
        const float* base = sa + ((size_t)(b*16 + o)*DPT)*HW + tid;
        float acc = 0.f;
        #pragma unroll 4
        for (int d = 0; d < 128; ++d) acc += base[d*HW] * a_s[d];
        feat[(b*16 + o)*HW + tid] = acc > 0.f ? acc : 0.f;
    }
}

// ---------------------------------------------------------------------------
// conv4/conv5 2D: relu(conv2d(3x3,pad1)) twice. One block per batch.
// ---------------------------------------------------------------------------
__global__ void conv45_kernel(const float* __restrict__ feat2,
                              const float* __restrict__ w45, const float* __restrict__ b45,
                              float* __restrict__ feat3, float* __restrict__ feat4)
{
    const int b = blockIdx.x, tid = threadIdx.x;
    __shared__ float fa[FEAT_SZ], fb[FEAT_SZ];
    for (int t = tid; t < FEAT_SZ; t += 128) fa[t] = feat2[b*FEAT_SZ + t];
    __syncthreads();
    if (tid < HW) {
        int h = tid / 11, w = tid - h*11;
        for (int o = 0; o < 16; o++) {
            float acc = b45[o];
            for (int c = 0; c < 16; c++)
                #pragma unroll
                for (int kh = 0; kh < 3; kh++) {
                    int hh = h + kh - 1; if (hh < 0 || hh >= 11) continue;
                    #pragma unroll
                    for (int kw = 0; kw < 3; kw++) {
                        int ww2 = w + kw - 1; if (ww2 < 0 || ww2 >= 11) continue;
                        acc += fa[c*HW + hh*11 + ww2] * w45[(o*16 + c)*9 + kh*3 + kw];
                    }
                }
            float v = acc > 0.f ? acc : 0.f;
            fb[o*HW + tid] = v;
            feat3[b*FEAT_SZ + o*HW + tid] = v;
        }
    }
    __syncthreads();
    if (tid < HW) {
        int h = tid / 11, w = tid - h*11;
        for (int o = 0; o < 16; o++) {
            float acc = b45[16 + o];
            for (int c = 0; c < 16; c++)
                #pragma unroll
                for (int kh = 0; kh < 3; kh++) {
                    int hh = h + kh - 1; if (hh < 0 || hh >= 11) continue;
                    #pragma unroll
                    for (int kw = 0; kw < 3; kw++) {
                        int ww2 = w + kw - 1; if (ww2 < 0 || ww2 >= 11) continue;
                        acc += fb[c*HW + hh*11 + ww2] * w45[2304 + (o*16 + c)*9 + kh*3 + kw];
                    }
                }
            float v = acc > 0.f ? acc : 0.f;
            feat4[b*FEAT_SZ + o*HW + tid] = v;
        }
    }
}

// ---------------------------------------------------------------------------
// Side head: per (side i, batch b). Sideout, seg conv, top-5 similar sum,
// receptive-field-reduced sp branch (only 7x7 ratio patch matters), fuse.
// ---------------------------------------------------------------------------
__global__ void side_kernel(const float* __restrict__ x, const float* __restrict__ feat,
    const float* __restrict__ sw,  const float* __restrict__ sb,
    const float* __restrict__ sow, const float* __restrict__ sob,
    const float* __restrict__ wa,  const float* __restrict__ ba,
    const float* __restrict__ wb,  const float* __restrict__ bbv,
    const float* __restrict__ ssw, const float* __restrict__ ssb,
    const float* __restrict__ fuse, float* __restrict__ out)
{
    const int i = blockIdx.x, b = blockIdx.y, tid = threadIdx.x;
    __shared__ float f_s[FEAT_SZ], act_s[HW], diff_s[HW], s_arr[128], xc[128], y1_s[144], y2_s[16];
    __shared__ int idx_s[5];

    for (int t = tid; t < FEAT_SZ; t += 128)
        f_s[t] = feat[i*(BB*FEAT_SZ) + b*FEAT_SZ + t];
    __syncthreads();

    // seg conv (no relu)
    if (tid < HW) {
        int h = tid / 11, w = tid - h*11;
        float acc = sb[i];
        for (int c = 0; c < 16; c++)
            #pragma unroll
            for (int kh = 0; kh < 3; kh++) {
                int hh = h + kh - 1; if (hh < 0 || hh >= 11) continue;
                #pragma unroll
                for (int kw = 0; kw < 3; kw++) {
                    int ww2 = w + kw - 1; if (ww2 < 0 || ww2 >= 11) continue;
                    acc += f_s[c*HW + hh*11 + ww2] * sw[(i*16 + c)*9 + kh*3 + kw];
                }
            }
        act_s[tid] = acc;
    }
    __syncthreads();
    if (tid < HW) diff_s[tid] = fabsf(act_s[tid] - act_s[60]);
    __syncthreads();
    // top-5 smallest diff, stable (lowest index on ties) — matches jax top_k(-diff)
    if (tid == 0) {
        for (int j = 0; j < 5; j++) {
            float best = 3.4e38f; int bi = 0;
            for (int p = 0; p < HW; p++) { float d = diff_s[p]; if (d < best) { best = d; bi = p; } }
            idx_s[j] = bi; diff_s[bi] = 3.4e38f;
        }
    }
    __syncthreads();
    // similar-sum s[c] and center xc[c]
    {
        float s = 0.f;
        const float* xb = x + (size_t)(b*128 + tid)*HW;
        #pragma unroll
        for (int j = 0; j < 5; j++) s += xb[idx_s[j]];
        s_arr[tid] = s;
        xc[tid] = xb[60];
    }
    __syncthreads();
    // y1 at the 9 positions {62,64,66}^2 feeding the dil-2 conv center
    for (int t = tid; t < 144; t += 128) {
        int o = t / 9, j = t - o*9;
        int pj = 62 + 2*(j/3), qj = 62 + 2*(j%3);
        float acc = ba[i*16 + o];
        #pragma unroll
        for (int ch = 0; ch < 2; ch++) {
            const float* num = ch ? xc : s_arr;
            #pragma unroll
            for (int eh = 0; eh < 3; eh++)
                #pragma unroll
                for (int ew = 0; ew < 3; ew++) {
                    int r = pj + eh - 1, c = qj + ew - 1;
                    float den = num[c];
                    den = fabsf(den) < 0.01f ? 0.01f : den;
                    float img = num[r] / den;
                    acc += img * wa[(((i*16 + o)*2 + ch)*3 + eh)*3 + ew];
                }
        }
        y1_s[o*9 + j] = acc > 0.f ? acc : 0.f;
    }
    __syncthreads();
    // y2 center (dil-2 conv), relu
    if (tid < 16) {
        float acc = bbv[i*16 + tid];
        for (int c = 0; c < 16; c++)
            #pragma unroll
            for (int j = 0; j < 9; j++)
                acc += y1_s[c*9 + j] * wb[((i*16 + tid)*16 + c)*9 + j];
        y2_s[tid] = acc > 0.f ? acc : 0.f;
    }
    __syncthreads();
    // sideouts + fuse
    if (tid < 16) {
        float sa_v = sob[i*16 + tid];
        for (int k = 0; k < 16; k++) sa_v += f_s[k*HW + 60] * sow[(i*16 + tid)*16 + k];
        float sp_v = ssb[i*16 + tid];
        for (int c = 0; c < 16; c++) sp_v += y2_s[c] * ssw[(i*16 + tid)*16 + c];
        atomicAdd(&out[b*16 + tid], fuse[i]*sa_v + fuse[5 + i]*sp_v);
    }
}

__global__ void zero_kernel(float* out, int n)
{
    int t = blockIdx.x*blockDim.x + threadIdx.x;
    if (t < n) out[t] = 0.f;
}

// ---------------------------------------------------------------------------
extern "C" void kernel_launch(void* const* d_in, const int* in_sizes, int n_in,
                              void* d_out, int out_size)
{
    const float* x      = (const float*)d_in[0];
    const float* w3d1   = (const float*)d_in[1];
    const float* b3d1   = (const float*)d_in[2];
    const float* w3d23  = (const float*)d_in[3];
    const float* b3d23  = (const float*)d_in[4];
    const float* cpr_w  = (const float*)d_in[5];
    const float* w2d45  = (const float*)d_in[6];
    const float* b2d45  = (const float*)d_in[7];
    const float* seg_w  = (const float*)d_in[8];
    const float* seg_b  = (const float*)d_in[9];
    const float* so_w   = (const float*)d_in[10];
    const float* so_b   = (const float*)d_in[11];
    const float* sp_wa  = (const float*)d_in[12];
    const float* sp_ba  = (const float*)d_in[13];
    const float* sp_wb  = (const float*)d_in[14];
    const float* sp_bb  = (const float*)d_in[15];
    const float* sp_sw  = (const float*)d_in[16];
    const float* sp_sb  = (const float*)d_in[17];
    const float* fuse   = (const float*)d_in[18];
    float* out = (float*)d_out;

    float *sa1, *sa2, *sa3, *feat;
    cudaGetSymbolAddress((void**)&sa1,  g_sa1);
    cudaGetSymbolAddress((void**)&sa2,  g_sa2);
    cudaGetSymbolAddress((void**)&sa3,  g_sa3);
    cudaGetSymbolAddress((void**)&feat, g_feat);

    // smem: non-dup weights chunk (float) + depth-pair input chunk (float2)
    const int SMEM16 = 4*63*16*4 + 4*13*169*8;   // 16,128 + 70,304 = 86,432 B (2 blocks/SM)
    const int SMEM1  = 1*63*16*4 + 1*13*169*8;   // 21,608 B
    cudaFuncSetAttribute((const void*)conv3d4_kernel<16,4>, cudaFuncAttributeMaxDynamicSharedMemorySize, SMEM16);
    cudaFuncSetAttribute((const void*)conv3d4_kernel<1,1>,  cudaFuncAttributeMaxDynamicSharedMemorySize, SMEM1);

    zero_kernel<<<(out_size + 255)/256, 256>>>(out, out_size);

    conv3d4_kernel<1,1><<<dim3(16, BB), 256, SMEM1>>>(x, w3d1, b3d1, sa1);
    cpr_kernel<<<dim3(16, BB), 128>>>(sa1, cpr_w + 0*2048, feat + 0*(BB*FEAT_SZ));

    conv3d4_kernel<16,4><<<dim3(16, BB), 256, SMEM16>>>(sa1, w3d23, b3d23, sa2);
    cpr_kernel<<<dim3(16, BB), 128>>>(sa2, cpr_w + 1*2048, feat + 1*(BB*FEAT_SZ));

    conv3d4_kernel<16,4><<<dim3(16, BB), 256, SMEM16>>>(sa2, w3d23 + 16128, b3d23 + 16, sa3);
    cpr_kernel<<<dim3(16, BB), 128>>>(sa3, cpr_w + 2*2048, feat + 2*(BB*FEAT_SZ));

    conv45_kernel<<<BB, 128>>>(feat + 2*(BB*FEAT_SZ), w2d45, b2d45,
                               feat + 3*(BB*FEAT_SZ), feat + 4*(BB*FEAT_SZ));

    side_kernel<<<dim3(5, BB), 128>>>(x, feat, seg_w, seg_b, so_w, so_b,
                                      sp_wa, sp_ba, sp_wb, sp_bb, sp_sw, sp_sb,
                                      fuse, out);
}